// round 4
// baseline (speedup 1.0000x reference)
#include <cuda_runtime.h>

#define NHX 64
#define NHY 64
#define NU  512
#define NV  512
#define LCH 16
#define NPLANES 6

#define CAPN 1000000
#define TILE_SHIFT 3                         // 8x8 uv cells per tile
#define NBUCKETS (8 * 64 * 64)               // m x utile x vtile = 32768

__device__ int    g_count[NBUCKETS];         // zeroed at load; scan re-zeroes each call
__device__ int    g_ptr[NBUCKETS];
__device__ float4 g_rec[CAPN];               // {hx, hy, u, v} in sorted order
__device__ int    g_idx[CAPN];               // pt | (m << 24)

// ---------------- sort pipeline (round-2 shape: 1 pt/thread) ----------------

__device__ __forceinline__ int bucket_of(int mi, float uu, float vv) {
    int uc = (int)(uu * (float)NU); if (uc > NU - 1) uc = NU - 1;
    int vc = (int)(vv * (float)NV); if (vc > NV - 1) vc = NV - 1;
    return (mi << 12) | ((uc >> TILE_SHIFT) << 6) | (vc >> TILE_SHIFT);
}

__global__ void __launch_bounds__(256)
hist_kernel(const int* __restrict__ m,
            const float* __restrict__ u,
            const float* __restrict__ v, int N) {
    int pt = blockIdx.x * blockDim.x + threadIdx.x;
    if (pt >= N) return;
    atomicAdd(&g_count[bucket_of(m[pt], u[pt], v[pt])], 1);
}

// single block 1024 threads, 32 buckets each; re-zeroes g_count for the next call
__global__ void scan_kernel() {
    __shared__ int sh[1024];
    int t = threadIdx.x;
    int base = t * 32;
    int c[32];
    int s = 0;
#pragma unroll
    for (int i = 0; i < 32; i++) { c[i] = g_count[base + i]; s += c[i]; }
    sh[t] = s;
    __syncthreads();
    for (int off = 1; off < 1024; off <<= 1) {
        int val = (t >= off) ? sh[t - off] : 0;
        __syncthreads();
        sh[t] += val;
        __syncthreads();
    }
    int ex = sh[t] - s;
#pragma unroll
    for (int i = 0; i < 32; i++) {
        g_ptr[base + i] = ex;
        ex += c[i];
        g_count[base + i] = 0;
    }
}

__global__ void __launch_bounds__(256)
scatter_kernel(const int* __restrict__ m,
               const float* __restrict__ h,
               const float* __restrict__ u,
               const float* __restrict__ v, int N) {
    int pt = blockIdx.x * blockDim.x + threadIdx.x;
    if (pt >= N) return;
    int   mi = m[pt];
    float uu = u[pt], vv = v[pt];
    float hx = h[2 * pt], hy = h[2 * pt + 1];
    int pos = atomicAdd(&g_ptr[bucket_of(mi, uu, vv)], 1);
    __stcs(&g_rec[pos], make_float4(hx, hy, uu, vv));
    __stcs(&g_idx[pos], pt | (mi << 24));
}

// ---------------- interpolation ----------------

__device__ __forceinline__ void axis(float ind, int I, int& i1, int& i2, float& fr) {
    if (ind == (float)I) ind = (float)(I - 1);
    i1 = (int)ind;
    fr = ind - (float)i1;
    i2 = i1 + 1;
    if (i2 == I) i2 = 0;
}

// i-direction lerp of one float4 slice at a single j column.
// Matches reference: val = F[i1,j]*(1-ir) + F[i2,j]*ir
__device__ __forceinline__ float4 lerp_i(const float* __restrict__ F,
                                         int mi, int I, int J,
                                         int i1, int i2, float ir,
                                         int j, int qq) {
    const float4* A = reinterpret_cast<const float4*>(F) + ((mi * I + i1) * J + j) * 4 + qq;
    const float4* B = reinterpret_cast<const float4*>(F) + ((mi * I + i2) * J + j) * 4 + qq;
    float4 a = __ldg(A);
    float4 b = __ldg(B);
    float o = 1.0f - ir;
    float4 r;
    r.x = a.x * o + b.x * ir;
    r.y = a.y * o + b.y * ir;
    r.z = a.z * o + b.z * ir;
    r.w = a.w * o + b.w * ir;
    return r;
}

// j-blend across the lane pair (q ^ 4). lo lanes hold the j1 value, hi lanes j2.
__device__ __forceinline__ float4 jblend(float4 t, float jr, bool lo) {
    float4 oth;
    oth.x = __shfl_xor_sync(0xffffffffu, t.x, 4);
    oth.y = __shfl_xor_sync(0xffffffffu, t.y, 4);
    oth.z = __shfl_xor_sync(0xffffffffu, t.z, 4);
    oth.w = __shfl_xor_sync(0xffffffffu, t.w, 4);
    float4 top = lo ? t : oth;   // j1 value
    float4 bot = lo ? oth : t;   // j2 value
    float o = 1.0f - jr;
    float4 r;
    r.x = top.x * o + bot.x * jr;
    r.y = top.y * o + bot.y * jr;
    r.z = top.z * o + bot.z * jr;
    r.w = top.w * o + bot.w * jr;
    return r;
}

__global__ void __launch_bounds__(256)
triplane_sorted_kernel(const float* __restrict__ Fxy,
                       const float* __restrict__ Fxu,
                       const float* __restrict__ Fxv,
                       const float* __restrict__ Fyu,
                       const float* __restrict__ Fyv,
                       const float* __restrict__ Fuv,
                       float4*      __restrict__ out,
                       int N) {
    int gid = blockIdx.x * blockDim.x + threadIdx.x;
    int p   = gid >> 3;          // sorted point index
    int q   = gid & 7;           // lane role: 0-3 = j1 side, 4-7 = j2 side
    int qq  = q & 3;             // float4 slice of the 16 channels
    bool lo = (q < 4);
    if (p >= N) return;

    float4 rec = __ldcs(&g_rec[p]);
    int packed = __ldcs(&g_idx[p]);
    int pt = packed & 0x00FFFFFF;
    int mi = packed >> 24;

    float ind_hx = (rec.x + 1.0f) / 2.0f * (float)NHX;
    float ind_hy = (rec.y + 1.0f) / 2.0f * (float)NHY;
    float ind_u  = rec.z * (float)NU;
    float ind_v  = rec.w * (float)NV;

    int x1, x2, y1, y2, u1, u2, v1, v2;
    float xr, yr, ur, vr;
    axis(ind_hx, NHX, x1, x2, xr);
    axis(ind_hy, NHY, y1, y2, yr);
    axis(ind_u,  NU,  u1, u2, ur);
    axis(ind_v,  NV,  v1, v2, vr);

    float4* o = out + (size_t)pt * (NPLANES * (LCH / 4));

    // plane p: i-axis lerp locally, j corner chosen by lane half, j-blend via shfl.
    // lo lanes store planes 0..2, hi lanes store planes 3..5 (all lanes compute all).
    {   // plane 0: (x, y)
        int js = lo ? y1 : y2;
        float4 r = jblend(lerp_i(Fxy, mi, NHX, NHY, x1, x2, xr, js, qq), yr, lo);
        if (lo) __stcs(&o[0 * 4 + qq], r);
    }
    {   // plane 1: (x, u)
        int js = lo ? u1 : u2;
        float4 r = jblend(lerp_i(Fxu, mi, NHX, NU, x1, x2, xr, js, qq), ur, lo);
        if (lo) __stcs(&o[1 * 4 + qq], r);
    }
    {   // plane 2: (x, v)
        int js = lo ? v1 : v2;
        float4 r = jblend(lerp_i(Fxv, mi, NHX, NV, x1, x2, xr, js, qq), vr, lo);
        if (lo) __stcs(&o[2 * 4 + qq], r);
    }
    {   // plane 3: (y, u)
        int js = lo ? u1 : u2;
        float4 r = jblend(lerp_i(Fyu, mi, NHY, NU, y1, y2, yr, js, qq), ur, lo);
        if (!lo) __stcs(&o[3 * 4 + qq], r);
    }
    {   // plane 4: (y, v)
        int js = lo ? v1 : v2;
        float4 r = jblend(lerp_i(Fyv, mi, NHY, NV, y1, y2, yr, js, qq), vr, lo);
        if (!lo) __stcs(&o[4 * 4 + qq], r);
    }
    {   // plane 5: (u, v)
        int js = lo ? v1 : v2;
        float4 r = jblend(lerp_i(Fuv, mi, NU, NV, u1, u2, ur, js, qq), vr, lo);
        if (!lo) __stcs(&o[5 * 4 + qq], r);
    }
}

// Fallback if N exceeds static scratch (no sort; same 8-lane scheme reading raw inputs)
__global__ void __launch_bounds__(256)
triplane_direct_kernel(const int*   __restrict__ m,
                       const float* __restrict__ h,
                       const float* __restrict__ u,
                       const float* __restrict__ v,
                       const float* __restrict__ Fxy,
                       const float* __restrict__ Fxu,
                       const float* __restrict__ Fxv,
                       const float* __restrict__ Fyu,
                       const float* __restrict__ Fyv,
                       const float* __restrict__ Fuv,
                       float4*      __restrict__ out,
                       int N) {
    int gid = blockIdx.x * blockDim.x + threadIdx.x;
    int p   = gid >> 3;
    int q   = gid & 7;
    int qq  = q & 3;
    bool lo = (q < 4);
    if (p >= N) return;

    int   mi = m[p];
    float ind_hx = (h[2 * p] + 1.0f) / 2.0f * (float)NHX;
    float ind_hy = (h[2 * p + 1] + 1.0f) / 2.0f * (float)NHY;
    float ind_u  = u[p] * (float)NU;
    float ind_v  = v[p] * (float)NV;

    int x1, x2, y1, y2, u1, u2, v1, v2;
    float xr, yr, ur, vr;
    axis(ind_hx, NHX, x1, x2, xr);
    axis(ind_hy, NHY, y1, y2, yr);
    axis(ind_u,  NU,  u1, u2, ur);
    axis(ind_v,  NV,  v1, v2, vr);

    float4* o = out + (size_t)p * (NPLANES * (LCH / 4));

    { int js = lo ? y1 : y2;
      float4 r = jblend(lerp_i(Fxy, mi, NHX, NHY, x1, x2, xr, js, qq), yr, lo);
      if (lo) __stcs(&o[0 * 4 + qq], r); }
    { int js = lo ? u1 : u2;
      float4 r = jblend(lerp_i(Fxu, mi, NHX, NU, x1, x2, xr, js, qq), ur, lo);
      if (lo) __stcs(&o[1 * 4 + qq], r); }
    { int js = lo ? v1 : v2;
      float4 r = jblend(lerp_i(Fxv, mi, NHX, NV, x1, x2, xr, js, qq), vr, lo);
      if (lo) __stcs(&o[2 * 4 + qq], r); }
    { int js = lo ? u1 : u2;
      float4 r = jblend(lerp_i(Fyu, mi, NHY, NU, y1, y2, yr, js, qq), ur, lo);
      if (!lo) __stcs(&o[3 * 4 + qq], r); }
    { int js = lo ? v1 : v2;
      float4 r = jblend(lerp_i(Fyv, mi, NHY, NV, y1, y2, yr, js, qq), vr, lo);
      if (!lo) __stcs(&o[4 * 4 + qq], r); }
    { int js = lo ? v1 : v2;
      float4 r = jblend(lerp_i(Fuv, mi, NU, NV, u1, u2, ur, js, qq), vr, lo);
      if (!lo) __stcs(&o[5 * 4 + qq], r); }
}

extern "C" void kernel_launch(void* const* d_in, const int* in_sizes, int n_in,
                              void* d_out, int out_size) {
    // order: r, m, h, u, v, Fxy, Fxu, Fxv, Fyu, Fyv, Fuv   (r unused)
    const int*   m   = (const int*)  d_in[1];
    const float* h   = (const float*)d_in[2];
    const float* u   = (const float*)d_in[3];
    const float* v   = (const float*)d_in[4];
    const float* Fxy = (const float*)d_in[5];
    const float* Fxu = (const float*)d_in[6];
    const float* Fxv = (const float*)d_in[7];
    const float* Fyu = (const float*)d_in[8];
    const float* Fyv = (const float*)d_in[9];
    const float* Fuv = (const float*)d_in[10];

    int N = in_sizes[1];
    int tpb = 256;

    if (N <= CAPN) {
        hist_kernel<<<(N + tpb - 1) / tpb, tpb>>>(m, u, v, N);
        scan_kernel<<<1, 1024>>>();
        scatter_kernel<<<(N + tpb - 1) / tpb, tpb>>>(m, h, u, v, N);

        long long tt = (long long)N * 8;
        triplane_sorted_kernel<<<(int)((tt + tpb - 1) / tpb), tpb>>>(
            Fxy, Fxu, Fxv, Fyu, Fyv, Fuv, (float4*)d_out, N);
    } else {
        long long tt = (long long)N * 8;
        triplane_direct_kernel<<<(int)((tt + tpb - 1) / tpb), tpb>>>(
            m, h, u, v, Fxy, Fxu, Fxv, Fyu, Fyv, Fuv, (float4*)d_out, N);
    }
}

// round 5
// speedup vs baseline: 1.2936x; 1.2936x over previous
#include <cuda_runtime.h>

#define NHX 64
#define NHY 64
#define NU  512
#define NV  512
#define LCH 16
#define NPLANES 6

#define CAPN 1000000
#define TILE_SHIFT 4                 // 16x16 uv cells per tile
#define TPD 32                       // tiles per dim (512 >> 4)
#define NB (8 * TPD * TPD)           // 8192 buckets
#define CAP 192                      // slots per bucket (mean ~122 at N=1M)

__device__ int    g_cnt[NB];                 // per-bucket counts (zeroed each launch)
__device__ float4 g_rec[NB * CAP];           // {hx, hy, u, v}
__device__ int    g_pt [NB * CAP];           // pt | (m << 24)
__device__ int    g_ovf_cnt;                 // overflow cursor
__device__ int    g_ovf_pt[CAPN];            // overflow point ids

// ---------------- bucketing ----------------

__device__ __forceinline__ int bucket_of(int mi, float uu, float vv) {
    int uc = (int)(uu * (float)NU); if (uc > NU - 1) uc = NU - 1;
    int vc = (int)(vv * (float)NV); if (vc > NV - 1) vc = NV - 1;
    return (mi << 10) | ((uc >> TILE_SHIFT) << 5) | (vc >> TILE_SHIFT);
}

__global__ void zero_kernel() {
    int i = blockIdx.x * blockDim.x + threadIdx.x;
    if (i < NB) g_cnt[i] = 0;
    if (i == 0) g_ovf_cnt = 0;
}

__global__ void __launch_bounds__(256)
scatter_kernel(const int* __restrict__ m,
               const float* __restrict__ h,
               const float* __restrict__ u,
               const float* __restrict__ v, int N) {
    int pt = blockIdx.x * blockDim.x + threadIdx.x;
    if (pt >= N) return;
    int   mi = m[pt];
    float uu = u[pt], vv = v[pt];
    float hx = h[2 * pt], hy = h[2 * pt + 1];
    int b = bucket_of(mi, uu, vv);
    int pos = atomicAdd(&g_cnt[b], 1);
    if (pos < CAP) {
        __stcs(&g_rec[b * CAP + pos], make_float4(hx, hy, uu, vv));
        __stcs(&g_pt [b * CAP + pos], pt | (mi << 24));
    } else {
        int o = atomicAdd(&g_ovf_cnt, 1);
        if (o < CAPN) g_ovf_pt[o] = pt;
    }
}

// ---------------- interpolation core ----------------

__device__ __forceinline__ void axis(float ind, int I, int& i1, int& i2, float& fr) {
    if (ind == (float)I) ind = (float)(I - 1);
    i1 = (int)ind;
    fr = ind - (float)i1;
    i2 = i1 + 1;
    if (i2 == I) i2 = 0;
}

__device__ __forceinline__ float4 bilerp4(const float* __restrict__ F,
                                          int mi, int I, int J,
                                          int i1, int i2, float ir,
                                          int j1, int j2, float jr, int q) {
    int rowA = (mi * I + i1) * J;
    int rowB = (mi * I + i2) * J;
    const float4* p11 = reinterpret_cast<const float4*>(F) + (rowA + j1) * 4 + q;
    const float4* p21 = reinterpret_cast<const float4*>(F) + (rowB + j1) * 4 + q;
    const float4* p12 = reinterpret_cast<const float4*>(F) + (rowA + j2) * 4 + q;
    const float4* p22 = reinterpret_cast<const float4*>(F) + (rowB + j2) * 4 + q;
    float4 a = __ldg(p11);
    float4 b = __ldg(p21);
    float4 c = __ldg(p12);
    float4 d = __ldg(p22);
    float omi = 1.0f - ir, omj = 1.0f - jr;
    float4 out;
    out.x = (a.x * omi + b.x * ir) * omj + (c.x * omi + d.x * ir) * jr;
    out.y = (a.y * omi + b.y * ir) * omj + (c.y * omi + d.y * ir) * jr;
    out.z = (a.z * omi + b.z * ir) * omj + (c.z * omi + d.z * ir) * jr;
    out.w = (a.w * omi + b.w * ir) * omj + (c.w * omi + d.w * ir) * jr;
    return out;
}

__device__ __forceinline__ void interp_point(float hx, float hy, float uu, float vv,
                                             int mi, int pt, int q,
                                             const float* __restrict__ Fxy,
                                             const float* __restrict__ Fxu,
                                             const float* __restrict__ Fxv,
                                             const float* __restrict__ Fyu,
                                             const float* __restrict__ Fyv,
                                             const float* __restrict__ Fuv,
                                             float4* __restrict__ out) {
    float ind_hx = (hx + 1.0f) / 2.0f * (float)NHX;
    float ind_hy = (hy + 1.0f) / 2.0f * (float)NHY;
    float ind_u  = uu * (float)NU;
    float ind_v  = vv * (float)NV;

    int x1, x2, y1, y2, u1, u2, v1, v2;
    float xr, yr, ur, vr;
    axis(ind_hx, NHX, x1, x2, xr);
    axis(ind_hy, NHY, y1, y2, yr);
    axis(ind_u,  NU,  u1, u2, ur);
    axis(ind_v,  NV,  v1, v2, vr);

    float4* o = out + (size_t)pt * (NPLANES * (LCH / 4));

    __stcs(&o[0 * 4 + q], bilerp4(Fxy, mi, NHX, NHY, x1, x2, xr, y1, y2, yr, q));
    __stcs(&o[1 * 4 + q], bilerp4(Fxu, mi, NHX, NU,  x1, x2, xr, u1, u2, ur, q));
    __stcs(&o[2 * 4 + q], bilerp4(Fxv, mi, NHX, NV,  x1, x2, xr, v1, v2, vr, q));
    __stcs(&o[3 * 4 + q], bilerp4(Fyu, mi, NHY, NU,  y1, y2, yr, u1, u2, ur, q));
    __stcs(&o[4 * 4 + q], bilerp4(Fyv, mi, NHY, NV,  y1, y2, yr, v1, v2, vr, q));
    __stcs(&o[5 * 4 + q], bilerp4(Fuv, mi, NU,  NV,  u1, u2, ur, v1, v2, vr, q));
}

// ---------------- main kernels ----------------

#define SLOTS_PER_BLOCK 64                    // 256 threads / 4 lanes
#define BLOCKS_PER_BUCKET (CAP / SLOTS_PER_BLOCK)   // 3

__global__ void __launch_bounds__(256)
triplane_bucket_kernel(const float* __restrict__ Fxy,
                       const float* __restrict__ Fxu,
                       const float* __restrict__ Fxv,
                       const float* __restrict__ Fyu,
                       const float* __restrict__ Fyv,
                       const float* __restrict__ Fuv,
                       float4*      __restrict__ out) {
    int bucket = blockIdx.x / BLOCKS_PER_BUCKET;
    int sbase  = (blockIdx.x % BLOCKS_PER_BUCKET) * SLOTS_PER_BLOCK;
    int t    = threadIdx.x;
    int slot = sbase + (t >> 2);
    int q    = t & 3;

    int cnt = g_cnt[bucket];
    if (cnt > CAP) cnt = CAP;
    if (slot >= cnt) return;

    float4 rec = __ldcs(&g_rec[bucket * CAP + slot]);
    int packed = __ldcs(&g_pt [bucket * CAP + slot]);
    int pt = packed & 0x00FFFFFF;
    int mi = packed >> 24;

    interp_point(rec.x, rec.y, rec.z, rec.w, mi, pt, q,
                 Fxy, Fxu, Fxv, Fyu, Fyv, Fuv, out);
}

// Processes overflow points (normally zero). Grid-stride over g_ovf_cnt * 4 lanes.
__global__ void __launch_bounds__(256)
triplane_overflow_kernel(const int*   __restrict__ m,
                         const float* __restrict__ h,
                         const float* __restrict__ u,
                         const float* __restrict__ v,
                         const float* __restrict__ Fxy,
                         const float* __restrict__ Fxu,
                         const float* __restrict__ Fxv,
                         const float* __restrict__ Fyu,
                         const float* __restrict__ Fyv,
                         const float* __restrict__ Fuv,
                         float4*      __restrict__ out) {
    int n = g_ovf_cnt;
    if (n > CAPN) n = CAPN;
    int total = n * 4;
    for (int i = blockIdx.x * blockDim.x + threadIdx.x; i < total;
         i += gridDim.x * blockDim.x) {
        int k  = i >> 2;
        int q  = i & 3;
        int pt = g_ovf_pt[k];
        int mi = m[pt];
        interp_point(h[2 * pt], h[2 * pt + 1], u[pt], v[pt], mi, pt, q,
                     Fxy, Fxu, Fxv, Fyu, Fyv, Fuv, out);
    }
}

// Fallback if N exceeds static scratch capacity: direct, unsorted.
__global__ void __launch_bounds__(256)
triplane_direct_kernel(const int*   __restrict__ m,
                       const float* __restrict__ h,
                       const float* __restrict__ u,
                       const float* __restrict__ v,
                       const float* __restrict__ Fxy,
                       const float* __restrict__ Fxu,
                       const float* __restrict__ Fxv,
                       const float* __restrict__ Fyu,
                       const float* __restrict__ Fyv,
                       const float* __restrict__ Fuv,
                       float4*      __restrict__ out,
                       int N) {
    int gid = blockIdx.x * blockDim.x + threadIdx.x;
    int pt  = gid >> 2;
    int q   = gid & 3;
    if (pt >= N) return;
    int mi = m[pt];
    interp_point(h[2 * pt], h[2 * pt + 1], u[pt], v[pt], mi, pt, q,
                 Fxy, Fxu, Fxv, Fyu, Fyv, Fuv, out);
}

extern "C" void kernel_launch(void* const* d_in, const int* in_sizes, int n_in,
                              void* d_out, int out_size) {
    // order: r, m, h, u, v, Fxy, Fxu, Fxv, Fyu, Fyv, Fuv   (r unused)
    const int*   m   = (const int*)  d_in[1];
    const float* h   = (const float*)d_in[2];
    const float* u   = (const float*)d_in[3];
    const float* v   = (const float*)d_in[4];
    const float* Fxy = (const float*)d_in[5];
    const float* Fxu = (const float*)d_in[6];
    const float* Fxv = (const float*)d_in[7];
    const float* Fyu = (const float*)d_in[8];
    const float* Fyv = (const float*)d_in[9];
    const float* Fuv = (const float*)d_in[10];

    int N = in_sizes[1];
    int tpb = 256;

    if (N <= CAPN) {
        zero_kernel<<<(NB + tpb - 1) / tpb, tpb>>>();
        scatter_kernel<<<(N + tpb - 1) / tpb, tpb>>>(m, h, u, v, N);
        triplane_bucket_kernel<<<NB * BLOCKS_PER_BUCKET, tpb>>>(
            Fxy, Fxu, Fxv, Fyu, Fyv, Fuv, (float4*)d_out);
        triplane_overflow_kernel<<<64, tpb>>>(
            m, h, u, v, Fxy, Fxu, Fxv, Fyu, Fyv, Fuv, (float4*)d_out);
    } else {
        long long tt = (long long)N * 4;
        triplane_direct_kernel<<<(int)((tt + tpb - 1) / tpb), tpb>>>(
            m, h, u, v, Fxy, Fxu, Fxv, Fyu, Fyv, Fuv, (float4*)d_out, N);
    }
}